// round 2
// baseline (speedup 1.0000x reference)
#include <cuda_runtime.h>
#include <cuda_bf16.h>
#include <math.h>

#define N_NODES 4096
#define E_EDGES 131072
#define DIM     128
#define DIM2    256
#define SDIM    128
#define RDIM    8
#define LDIM    16
#define HIDD    64
#define TOPKK   16
#define NEGV    (-1000000000.0f)

// ----------------- scratch (device globals; no allocation) ---------------
__device__ float    g_agg1[N_NODES*DIM];
__device__ float    g_hup [N_NODES*DIM2];
__device__ float    g_hloc[N_NODES*DIM2];
__device__ float    g_hid [N_NODES*HIDD];
__device__ float    g_m   [N_NODES];
__device__ int      g_mf  [N_NODES];
__device__ int      g_vlist[N_NODES];
__device__ int      g_Nv;
__device__ float    g_qv[N_NODES*SDIM];
__device__ float    g_kv[N_NODES*SDIM];
__device__ float    g_P1[N_NODES*SDIM];
__device__ float    g_P2[N_NODES*SDIM];
__device__ float    g_S [N_NODES*N_NODES];
__device__ int      g_vdc[N_NODES*TOPKK];
__device__ int      g_vdo[N_NODES*TOPKK];
__device__ float    g_sc [N_NODES*TOPKK];
__device__ float    g_ex [N_NODES*TOPKK];
__device__ float    g_shd[N_NODES*TOPKK];
__device__ float    g_rf [N_NODES*TOPKK*RDIM];
__device__ unsigned g_maxenc[N_NODES];
__device__ float    g_den[N_NODES];
__device__ float    g_aggH[N_NODES*DIM2];
__device__ float    g_hmup[N_NODES*DIM2];

// ----------------- helpers ---------------
__device__ __forceinline__ float wredsum(float v){
#pragma unroll
    for (int o=16;o>0;o>>=1) v += __shfl_xor_sync(0xffffffffu, v, o);
    return v;
}
__device__ __forceinline__ unsigned enc(float f){
    unsigned u=__float_as_uint(f);
    return (u&0x80000000u)? ~u : (u|0x80000000u);
}
__device__ __forceinline__ float dec(unsigned u){
    return (u&0x80000000u)? __uint_as_float(u & 0x7fffffffu) : __uint_as_float(~u);
}
__device__ __forceinline__ void red4(float* a, float x,float y,float z,float w){
    asm volatile("red.global.add.v4.f32 [%0], {%1,%2,%3,%4};"
                 :: "l"(a),"f"(x),"f"(y),"f"(z),"f"(w) : "memory");
}
__device__ __forceinline__ float sh_dot(float vx,float vy,float vz, const float* w){
    float n = sqrtf(vx*vx+vy*vy+vz*vz);
    float inv = 1.0f/(n+1e-9f);
    float x=vx*inv, y=vy*inv, z=vz*inv;
    return w[0]+w[1]*x+w[2]*y+w[3]*z
      + w[4]*x*x + w[5]*y*y + w[6]*z*z
      + w[7]*x*y + w[8]*x*z + w[9]*y*z
      + w[10]*x*x*x + w[11]*y*y*y + w[12]*z*z*z
      + w[13]*x*x*y + w[14]*y*y*z + w[15]*z*z*x;
}

// ----------------- fill / reset ---------------
__global__ void fill_k(){
    int i = blockIdx.x*blockDim.x + threadIdx.x;
    int stride = gridDim.x*blockDim.x;
    for (int j=i; j<N_NODES*DIM2; j+=stride){
        g_aggH[j]=0.f;
        if (j<N_NODES*DIM) g_agg1[j]=0.f;
        if (j<N_NODES){ g_den[j]=0.f; g_maxenc[j]=0x007FFFFFu; }
    }
}

// ----------------- stage 1: edge messages (gate * h[src] * shdot) ---------------
__global__ __launch_bounds__(256) void edge_msgs1(
    const float* __restrict__ h, const int* __restrict__ ei,
    const float* __restrict__ esh, const float* __restrict__ ef,
    const float* __restrict__ Wlr, const float* __restrict__ wlsh)
{
    __shared__ float sW[RDIM*DIM];
    __shared__ float swsh[LDIM];
    int tid = threadIdx.x;
    for (int i=tid;i<RDIM*DIM;i+=256) sW[i]=Wlr[i];
    if (tid<LDIM) swsh[tid]=wlsh[tid];
    __syncthreads();
    int e = blockIdx.x*8 + (tid>>5);
    int lane = tid & 31;
    if (e >= E_EDGES) return;
    int src = ei[e], dst = ei[E_EDGES+e];
    float t = (lane<LDIM)? esh[e*LDIM+lane]*swsh[lane] : 0.f;
    float shd = wredsum(t);
    float efv = (lane<RDIM)? ef[e*RDIM+lane] : 0.f;
    int base = lane<<2;
    float g0=0.f,g1=0.f,g2=0.f,g3=0.f;
#pragma unroll
    for (int r=0;r<RDIM;r++){
        float er = __shfl_sync(0xffffffffu, efv, r);
        g0 += er*sW[r*DIM+base+0];
        g1 += er*sW[r*DIM+base+1];
        g2 += er*sW[r*DIM+base+2];
        g3 += er*sW[r*DIM+base+3];
    }
    float4 hv = *(const float4*)(h + src*DIM + base);
    red4(&g_agg1[dst*DIM+base], hv.x*g0*shd, hv.y*g1*shd, hv.z*g2*shd, hv.w*g3*shd);
}

// ----------------- generic SIMT fp32 GEMM (64x64 tile, 4x4 micro) ---------------
enum { EPI_NONE=0, EPI_SCORES=1, EPI_ADDPADH=2, EPI_BIASRELU=3, EPI_BIAS=4, EPI_FINAL=5 };

template<int EPI, bool TRANSB, bool GATHER>
__global__ __launch_bounds__(256)
void gemm_k(const float* __restrict__ A, int lda,
            const float* __restrict__ B, int ldb,
            float* __restrict__ C, int ldc,
            int M, int Nc, int K,
            const int* __restrict__ Mdyn,
            const int* __restrict__ gidx,
            const float* __restrict__ ep0,
            const float* __restrict__ ep1,
            float scale)
{
    if (Mdyn) M = *Mdyn;
    int NB = (EPI==EPI_SCORES) ? M : Nc;
    int by = blockIdx.y, bx = blockIdx.x;
    if (by*64 >= M) return;
    if (bx*64 >= NB) return;

    __shared__ float As[16][68];
    __shared__ float Bs[16][68];

    int tid = threadIdx.x;
    int tx = tid & 15, ty = tid >> 4;

    int aRow = tid >> 2;
    int aK4  = (tid & 3) << 2;
    int arow_g = by*64 + aRow;
    bool aok = arow_g < M;
    int arowIdx = 0;
    if (aok) arowIdx = GATHER ? gidx[arow_g] : arow_g;

    float acc[4][4];
#pragma unroll
    for (int i=0;i<4;i++)
#pragma unroll
        for (int j=0;j<4;j++) acc[i][j]=0.f;

    for (int k0=0; k0<K; k0+=16){
        float4 av = make_float4(0.f,0.f,0.f,0.f);
        if (aok) av = *(const float4*)(A + arowIdx*lda + k0 + aK4);
        As[aK4+0][aRow]=av.x; As[aK4+1][aRow]=av.y;
        As[aK4+2][aRow]=av.z; As[aK4+3][aRow]=av.w;
        if (!TRANSB){
            int bK = tid >> 4;
            int bN = (tid & 15) << 2;
            float4 bv = *(const float4*)(B + (k0+bK)*ldb + bx*64 + bN);
            *(float4*)&Bs[bK][bN] = bv;
        } else {
            int bN = tid >> 2;
            int bK4 = (tid & 3) << 2;
            int bn_g = bx*64 + bN;
            float4 bv = make_float4(0.f,0.f,0.f,0.f);
            if (bn_g < NB) bv = *(const float4*)(B + bn_g*ldb + k0 + bK4);
            Bs[bK4+0][bN]=bv.x; Bs[bK4+1][bN]=bv.y;
            Bs[bK4+2][bN]=bv.z; Bs[bK4+3][bN]=bv.w;
        }
        __syncthreads();
#pragma unroll
        for (int k=0;k<16;k++){
            float4 a = *(const float4*)&As[k][ty<<2];
            float4 b = *(const float4*)&Bs[k][tx<<2];
            acc[0][0]+=a.x*b.x; acc[0][1]+=a.x*b.y; acc[0][2]+=a.x*b.z; acc[0][3]+=a.x*b.w;
            acc[1][0]+=a.y*b.x; acc[1][1]+=a.y*b.y; acc[1][2]+=a.y*b.z; acc[1][3]+=a.y*b.w;
            acc[2][0]+=a.z*b.x; acc[2][1]+=a.z*b.y; acc[2][2]+=a.z*b.z; acc[2][3]+=a.z*b.w;
            acc[3][0]+=a.w*b.x; acc[3][1]+=a.w*b.y; acc[3][2]+=a.w*b.z; acc[3][3]+=a.w*b.w;
        }
        __syncthreads();
    }

#pragma unroll
    for (int i=0;i<4;i++){
        int r = by*64 + (ty<<2) + i;
        if (r >= M) continue;
#pragma unroll
        for (int j=0;j<4;j++){
            int c = bx*64 + (tx<<2) + j;
            if (c >= NB) continue;
            float v = acc[i][j];
            if constexpr (EPI==EPI_SCORES){
                v *= scale;
                if (r==c) v = NEGV;
            } else if constexpr (EPI==EPI_ADDPADH){
                if (c < DIM) v += ep0[r*DIM + c];
            } else if constexpr (EPI==EPI_BIASRELU){
                v += ep0[c]; v = v>0.f ? v : 0.f;
            } else if constexpr (EPI==EPI_BIAS){
                v += ep0[c];
            } else if constexpr (EPI==EPI_FINAL){
                float hl = ep0[r*DIM2 + c];
                float mm = ep1[r];
                float mfv = (mm > 0.5f) ? 1.f : 0.f;
                v = (1.f-mm)*hl + mm*((v+hl)*mfv);
            }
            C[r*ldc + c] = v;
        }
    }
}

// ----------------- mask MLP output + sigmoid ---------------
__global__ void compute_m(const float* __restrict__ Wms2, const float* __restrict__ bms2)
{
    int row = blockIdx.x*4 + (threadIdx.x>>5);
    int lane = threadIdx.x & 31;
    if (row >= N_NODES) return;
    float s = g_hid[row*HIDD+lane]*Wms2[lane] + g_hid[row*HIDD+lane+32]*Wms2[lane+32];
    s = wredsum(s);
    if (lane==0){
        float z = s + bms2[0];
        float m = 1.f/(1.f+expf(-z));
        g_m[row] = m;
        g_mf[row] = (m > 0.5f) ? 1 : 0;
    }
}

// ----------------- ordered compaction of valid nodes ---------------
__global__ __launch_bounds__(1024) void scan_valid()
{
    __shared__ int cnt[1024];
    int t = threadIdx.x;
    int b = t*4;
    int l0=g_mf[b], l1=g_mf[b+1], l2=g_mf[b+2], l3=g_mf[b+3];
    int c = l0+l1+l2+l3;
    cnt[t]=c; __syncthreads();
    for (int off=1; off<1024; off<<=1){
        int v = cnt[t];
        int add = (t>=off)? cnt[t-off] : 0;
        __syncthreads();
        cnt[t] = v+add;
        __syncthreads();
    }
    int pos = cnt[t]-c;
    if (l0) g_vlist[pos++]=b;
    if (l1) g_vlist[pos++]=b+1;
    if (l2) g_vlist[pos++]=b+2;
    if (l3) g_vlist[pos++]=b+3;
    if (t==1023) g_Nv = cnt[1023];
}

// ----------------- per-row top-16 (tie -> lowest index, matches jax) ---------------
__global__ __launch_bounds__(128) void topk_k()
{
    int Nv = g_Nv;
    int vi = blockIdx.x;
    if (vi >= Nv) return;
    __shared__ float vals[N_NODES];
    __shared__ float rv[128];
    __shared__ int   ri[128];
    int tid = threadIdx.x;
    const float* row = &g_S[vi*N_NODES];
    for (int j=tid;j<Nv;j+=128) vals[j]=row[j];
    __syncthreads();
    for (int t=0;t<TOPKK;t++){
        float bv=-3.4e38f; int bi=0x7fffffff;
        for (int j=tid;j<Nv;j+=128){
            float v=vals[j];
            if (v>bv || (v==bv && j<bi)){bv=v;bi=j;}
        }
        rv[tid]=bv; ri[tid]=bi;
        __syncthreads();
        for (int off=64;off>0;off>>=1){
            if (tid<off){
                float ov=rv[tid+off]; int oi=ri[tid+off];
                if (ov>rv[tid] || (ov==rv[tid] && oi<ri[tid])){rv[tid]=ov;ri[tid]=oi;}
            }
            __syncthreads();
        }
        if (tid==0){
            int bj = ri[0];
            if (rv[0] > NEGV*0.5f){
                g_vdc[vi*TOPKK+t]=bj;
                g_vdo[vi*TOPKK+t]=g_vlist[bj];
            } else {
                g_vdc[vi*TOPKK+t]=-1;
                g_vdo[vi*TOPKK+t]=-1;
            }
            vals[bj] = -3.4e38f;
        }
        __syncthreads();
    }
}

// ----------------- virtual edge MLP score ---------------
__global__ __launch_bounds__(256) void vedge_mlp(
    const float* __restrict__ pos, const float* __restrict__ Wa1,
    const float* __restrict__ Wa2, const float* __restrict__ ba2,
    const float* __restrict__ whsh)
{
    __shared__ float sW1[RDIM*SDIM];
    __shared__ float sW2[SDIM];
    int tid=threadIdx.x;
    for (int i=tid;i<RDIM*SDIM;i+=256) sW1[i]=Wa1[2*SDIM*SDIM + i];
    for (int i=tid;i<SDIM;i+=256) sW2[i]=Wa2[i];
    __syncthreads();
    int Nv = g_Nv;
    int s = blockIdx.x*8 + (tid>>5);
    int lane = tid & 31;
    if (s >= Nv*TOPKK) return;
    int jo = g_vdo[s];
    if (jo < 0) return;
    int vi = s >> 4;
    int jc = g_vdc[s];
    int i  = g_vlist[vi];
    float dx = pos[i*3+0]-pos[jo*3+0];
    float dy = pos[i*3+1]-pos[jo*3+1];
    float dz = pos[i*3+2]-pos[jo*3+2];
    float r = sqrtf(dx*dx+dy*dy+dz*dz);
    float rf[8];
#pragma unroll
    for (int k=0;k<8;k++){ float cc=k*(5.0f/7.0f); float d=r-cc; rf[k]=expf(-4.0f*d*d); }
    if (lane < 8){
        float cc=lane*(5.0f/7.0f); float d=r-cc;
        g_rf[s*RDIM+lane] = expf(-4.0f*d*d);
    }
    if (lane==0) g_shd[s] = sh_dot(dx,dy,dz, whsh);
    float sum = 0.f;
#pragma unroll
    for (int u=0;u<4;u++){
        int d = lane + u*32;
        float hv = g_P1[vi*SDIM+d] + g_P2[jc*SDIM+d];
#pragma unroll
        for (int k=0;k<8;k++) hv += rf[k]*sW1[k*SDIM+d];
        hv = hv>0.f ? hv : 0.f;
        sum += hv*sW2[d];
    }
    sum = wredsum(sum);
    if (lane==0){
        float sc = sum + ba2[0];
        g_sc[s] = sc;
        atomicMax(&g_maxenc[jo], enc(sc));
    }
}

// ----------------- softmax denominator ---------------
__global__ void softmax2()
{
    int s = blockIdx.x*blockDim.x + threadIdx.x;
    int Nv = g_Nv;
    if (s >= Nv*TOPKK) return;
    int jo = g_vdo[s];
    if (jo < 0) return;
    float mx = dec(g_maxenc[jo]);
    float e = expf(g_sc[s]-mx);
    g_ex[s] = e;
    atomicAdd(&g_den[jo], e);
}

// ----------------- real-edge hierarchical messages (masked) ---------------
__global__ __launch_bounds__(256) void edge_msgsH(
    const float* __restrict__ pos, const int* __restrict__ ei,
    const float* __restrict__ Whr, const float* __restrict__ whsh)
{
    __shared__ float sW[RDIM*DIM2];
    __shared__ float swsh[LDIM];
    int tid=threadIdx.x;
    for (int i=tid;i<RDIM*DIM2;i+=256) sW[i]=Whr[i];
    if (tid<LDIM) swsh[tid]=whsh[tid];
    __syncthreads();
    int e = blockIdx.x*8 + (tid>>5);
    int lane = tid & 31;
    if (e >= E_EDGES) return;
    int src = ei[e], dst = ei[E_EDGES+e];
    if (!(g_mf[src] & g_mf[dst])) return;
    float dx = pos[src*3+0]-pos[dst*3+0];
    float dy = pos[src*3+1]-pos[dst*3+1];
    float dz = pos[src*3+2]-pos[dst*3+2];
    float r = sqrtf(dx*dx+dy*dy+dz*dz);
    float shd = sh_dot(dx,dy,dz, swsh);
    float rf[8];
#pragma unroll
    for (int k=0;k<8;k++){ float cc=k*(5.0f/7.0f); float d=r-cc; rf[k]=expf(-4.0f*d*d); }
    int base = lane*8;
    float g[8];
#pragma unroll
    for (int u=0;u<8;u++){
        float acc=0.f;
#pragma unroll
        for (int k=0;k<8;k++) acc += rf[k]*sW[k*DIM2+base+u];
        g[u]=acc;
    }
    float4 h0 = *(const float4*)&g_hloc[src*DIM2+base];
    float4 h1 = *(const float4*)&g_hloc[src*DIM2+base+4];
    red4(&g_aggH[dst*DIM2+base  ], h0.x*g[0]*shd, h0.y*g[1]*shd, h0.z*g[2]*shd, h0.w*g[3]*shd);
    red4(&g_aggH[dst*DIM2+base+4], h1.x*g[4]*shd, h1.y*g[5]*shd, h1.z*g[6]*shd, h1.w*g[7]*shd);
}

// ----------------- virtual-edge hierarchical messages ---------------
__global__ __launch_bounds__(256) void virt_msgs(const float* __restrict__ Whr)
{
    __shared__ float sW[RDIM*DIM2];
    int tid=threadIdx.x;
    for (int i=tid;i<RDIM*DIM2;i+=256) sW[i]=Whr[i];
    __syncthreads();
    int Nv = g_Nv;
    int s = blockIdx.x*8 + (tid>>5);
    int lane = tid & 31;
    if (s >= Nv*TOPKK) return;
    int jo = g_vdo[s];
    if (jo < 0) return;
    int vi = s >> 4;
    int i  = g_vlist[vi];
    float wv = g_ex[s]/(g_den[jo]+1e-12f);
    float shd = g_shd[s];
    float rf[8];
#pragma unroll
    for (int k=0;k<8;k++) rf[k]=g_rf[s*RDIM+k]*wv;
    int base = lane*8;
    float g[8];
#pragma unroll
    for (int u=0;u<8;u++){
        float acc=0.f;
#pragma unroll
        for (int k=0;k<8;k++) acc += rf[k]*sW[k*DIM2+base+u];
        g[u]=acc;
    }
    float4 h0 = *(const float4*)&g_hloc[i*DIM2+base];
    float4 h1 = *(const float4*)&g_hloc[i*DIM2+base+4];
    red4(&g_aggH[jo*DIM2+base  ], h0.x*g[0]*shd, h0.y*g[1]*shd, h0.z*g[2]*shd, h0.w*g[3]*shd);
    red4(&g_aggH[jo*DIM2+base+4], h1.x*g[4]*shd, h1.y*g[5]*shd, h1.z*g[6]*shd, h1.w*g[7]*shd);
}

// ----------------- launcher ---------------
extern "C" void kernel_launch(void* const* d_in, const int* in_sizes, int n_in,
                              void* d_out, int out_size)
{
    const float* h    = (const float*)d_in[0];
    const float* pos  = (const float*)d_in[1];
    const int*   ei   = (const int*)  d_in[2];
    const float* esh  = (const float*)d_in[3];
    const float* ef   = (const float*)d_in[4];
    const float* Wlr  = (const float*)d_in[6];
    const float* wlsh = (const float*)d_in[7];
    const float* Wlout= (const float*)d_in[8];
    const float* Wpl  = (const float*)d_in[9];
    const float* Wms1 = (const float*)d_in[10];
    const float* bms1 = (const float*)d_in[11];
    const float* Wms2 = (const float*)d_in[12];
    const float* bms2 = (const float*)d_in[13];
    const float* Wq   = (const float*)d_in[14];
    const float* Wk   = (const float*)d_in[15];
    const float* Wa1  = (const float*)d_in[16];
    const float* ba1  = (const float*)d_in[17];
    const float* Wa2  = (const float*)d_in[18];
    const float* ba2  = (const float*)d_in[19];
    const float* Whr  = (const float*)d_in[20];
    const float* whsh = (const float*)d_in[21];
    const float* Whout= (const float*)d_in[22];
    const float* Wph  = (const float*)d_in[23];
    float* out = (float*)d_out;

    float *p_agg1,*p_hup,*p_hloc,*p_hid,*p_qv,*p_kv,*p_P1,*p_P2,*p_S,*p_aggH,*p_hmup,*p_m;
    int *p_Nv,*p_vlist;
    cudaGetSymbolAddress((void**)&p_agg1, g_agg1);
    cudaGetSymbolAddress((void**)&p_hup , g_hup );
    cudaGetSymbolAddress((void**)&p_hloc, g_hloc);
    cudaGetSymbolAddress((void**)&p_hid , g_hid );
    cudaGetSymbolAddress((void**)&p_qv  , g_qv  );
    cudaGetSymbolAddress((void**)&p_kv  , g_kv  );
    cudaGetSymbolAddress((void**)&p_P1  , g_P1  );
    cudaGetSymbolAddress((void**)&p_P2  , g_P2  );
    cudaGetSymbolAddress((void**)&p_S   , g_S   );
    cudaGetSymbolAddress((void**)&p_aggH, g_aggH);
    cudaGetSymbolAddress((void**)&p_hmup, g_hmup);
    cudaGetSymbolAddress((void**)&p_m   , g_m   );
    cudaGetSymbolAddress((void**)&p_Nv  , g_Nv  );
    cudaGetSymbolAddress((void**)&p_vlist, g_vlist);

    const float scal = 0.088388347648318447f; // 1/sqrt(128)

    fill_k<<<1024,256>>>();
    edge_msgs1<<<E_EDGES/8,256>>>(h,ei,esh,ef,Wlr,wlsh);
    // h_up = agg1 @ W_loc_out
    gemm_k<EPI_NONE,false,false><<<dim3(4,64),256>>>(p_agg1,DIM, Wlout,DIM2, p_hup,DIM2,
        N_NODES,DIM2,DIM, nullptr,nullptr,nullptr,nullptr,0.f);
    // h_local = h_up @ W_prod_loc + pad(h)
    gemm_k<EPI_ADDPADH,false,false><<<dim3(4,64),256>>>(p_hup,DIM2, Wpl,DIM2, p_hloc,DIM2,
        N_NODES,DIM2,DIM2, nullptr,nullptr, h,nullptr,0.f);
    // hidden = relu(h_scalar @ W_ms1 + b_ms1)
    gemm_k<EPI_BIASRELU,false,false><<<dim3(1,64),256>>>(p_hloc,DIM2, Wms1,HIDD, p_hid,HIDD,
        N_NODES,HIDD,SDIM, nullptr,nullptr, bms1,nullptr,0.f);
    compute_m<<<1024,128>>>(Wms2,bms2);
    scan_valid<<<1,1024>>>();
    // gathered valid-row GEMMs
    gemm_k<EPI_NONE,false,true><<<dim3(2,64),256>>>(p_hloc,DIM2, Wq,SDIM, p_qv,SDIM,
        N_NODES,SDIM,SDIM, p_Nv, p_vlist, nullptr,nullptr,0.f);
    gemm_k<EPI_NONE,false,true><<<dim3(2,64),256>>>(p_hloc,DIM2, Wk,SDIM, p_kv,SDIM,
        N_NODES,SDIM,SDIM, p_Nv, p_vlist, nullptr,nullptr,0.f);
    gemm_k<EPI_BIAS,false,true><<<dim3(2,64),256>>>(p_hloc,DIM2, Wa1,SDIM, p_P1,SDIM,
        N_NODES,SDIM,SDIM, p_Nv, p_vlist, ba1,nullptr,0.f);
    gemm_k<EPI_NONE,false,true><<<dim3(2,64),256>>>(p_hloc,DIM2, Wa1+SDIM*SDIM,SDIM, p_P2,SDIM,
        N_NODES,SDIM,SDIM, p_Nv, p_vlist, nullptr,nullptr,0.f);
    // scores = qv @ kv^T * scale, diag=NEG (compact Nv x Nv)
    gemm_k<EPI_SCORES,true,false><<<dim3(64,64),256>>>(p_qv,SDIM, p_kv,SDIM, p_S,N_NODES,
        N_NODES,N_NODES,SDIM, p_Nv, nullptr, nullptr,nullptr, scal);
    topk_k<<<N_NODES,128>>>();
    vedge_mlp<<<N_NODES*TOPKK/8,256>>>(pos, Wa1, Wa2, ba2, whsh);
    softmax2<<<N_NODES*TOPKK/256,256>>>();
    edge_msgsH<<<E_EDGES/8,256>>>(pos,ei,Whr,whsh);
    virt_msgs<<<N_NODES*TOPKK/8,256>>>(Whr);
    // h_m_up = aggH @ W_h_out
    gemm_k<EPI_NONE,false,false><<<dim3(4,64),256>>>(p_aggH,DIM2, Whout,DIM2, p_hmup,DIM2,
        N_NODES,DIM2,DIM2, nullptr,nullptr,nullptr,nullptr,0.f);
    // out = (1-m)*h_local + m*((h_m_up@W_prod_h + h_local)*mf)
    gemm_k<EPI_FINAL,false,false><<<dim3(4,64),256>>>(p_hmup,DIM2, Wph,DIM2, out,DIM2,
        N_NODES,DIM2,DIM2, nullptr,nullptr, p_hloc, p_m, 0.f);
}

// round 3
// speedup vs baseline: 1.0581x; 1.0581x over previous
#include <cuda_runtime.h>
#include <cuda_bf16.h>
#include <math.h>

#define N_NODES 4096
#define E_EDGES 131072
#define DIM     128
#define DIM2    256
#define SDIM    128
#define RDIM    8
#define LDIM    16
#define HIDD    64
#define TOPKK   16
#define NEGV    (-1000000000.0f)

// ----------------- scratch (device globals; no allocation) ---------------
__device__ float    g_agg1[N_NODES*DIM];
__device__ float    g_hup [N_NODES*DIM2];
__device__ float    g_hloc[N_NODES*DIM2];
__device__ float    g_hid [N_NODES*HIDD];
__device__ float    g_m   [N_NODES];
__device__ int      g_mf  [N_NODES];
__device__ int      g_vlist[N_NODES];
__device__ int      g_Nv;
__device__ float    g_qv[N_NODES*SDIM];
__device__ float    g_kv[N_NODES*SDIM];
__device__ float    g_P1[N_NODES*SDIM];
__device__ float    g_P2[N_NODES*SDIM];
__device__ float    g_S [N_NODES*N_NODES];
__device__ int      g_vdc[N_NODES*TOPKK];
__device__ int      g_vdo[N_NODES*TOPKK];
__device__ float    g_sc [N_NODES*TOPKK];
__device__ float    g_ex [N_NODES*TOPKK];
__device__ float    g_shd[N_NODES*TOPKK];
__device__ float    g_rf [N_NODES*TOPKK*RDIM];
__device__ unsigned g_maxenc[N_NODES];
__device__ float    g_den[N_NODES];
__device__ float    g_aggH[N_NODES*DIM2];
__device__ float    g_hmup[N_NODES*DIM2];

// ----------------- helpers ---------------
__device__ __forceinline__ float wredsum(float v){
#pragma unroll
    for (int o=16;o>0;o>>=1) v += __shfl_xor_sync(0xffffffffu, v, o);
    return v;
}
__device__ __forceinline__ unsigned enc(float f){
    unsigned u=__float_as_uint(f);
    return (u&0x80000000u)? ~u : (u|0x80000000u);
}
__device__ __forceinline__ float dec(unsigned u){
    return (u&0x80000000u)? __uint_as_float(u & 0x7fffffffu) : __uint_as_float(~u);
}
__device__ __forceinline__ void red4(float* a, float x,float y,float z,float w){
    asm volatile("red.global.add.v4.f32 [%0], {%1,%2,%3,%4};"
                 :: "l"(a),"f"(x),"f"(y),"f"(z),"f"(w) : "memory");
}
__device__ __forceinline__ float sh_dot(float vx,float vy,float vz, const float* w){
    float n = sqrtf(vx*vx+vy*vy+vz*vz);
    float inv = 1.0f/(n+1e-9f);
    float x=vx*inv, y=vy*inv, z=vz*inv;
    return w[0]+w[1]*x+w[2]*y+w[3]*z
      + w[4]*x*x + w[5]*y*y + w[6]*z*z
      + w[7]*x*y + w[8]*x*z + w[9]*y*z
      + w[10]*x*x*x + w[11]*y*y*y + w[12]*z*z*z
      + w[13]*x*x*y + w[14]*y*y*z + w[15]*z*z*x;
}
__device__ __forceinline__ void split_tf32(float f, unsigned& hi, unsigned& lo){
    unsigned h; asm("cvt.rna.tf32.f32 %0, %1;" : "=r"(h) : "f"(f));
    float l = f - __uint_as_float(h);
    unsigned lu; asm("cvt.rna.tf32.f32 %0, %1;" : "=r"(lu) : "f"(l));
    hi = h; lo = lu;
}
#define MMA_TF32(c, a0,a1,a2,a3, b0,b1) \
  asm volatile("mma.sync.aligned.m16n8k8.row.col.f32.tf32.tf32.f32 " \
   "{%0,%1,%2,%3}, {%4,%5,%6,%7}, {%8,%9}, {%0,%1,%2,%3};" \
   : "+f"((c)[0]),"+f"((c)[1]),"+f"((c)[2]),"+f"((c)[3]) \
   : "r"(a0),"r"(a1),"r"(a2),"r"(a3),"r"(b0),"r"(b1))

// ----------------- fill / reset ---------------
__global__ void fill_k(){
    int i = blockIdx.x*blockDim.x + threadIdx.x;
    int stride = gridDim.x*blockDim.x;
    for (int j=i; j<N_NODES*DIM2; j+=stride){
        g_aggH[j]=0.f;
        if (j<N_NODES*DIM) g_agg1[j]=0.f;
        if (j<N_NODES){ g_den[j]=0.f; g_maxenc[j]=0x007FFFFFu; }
    }
}

// ----------------- stage 1: edge messages (gate * h[src] * shdot) ---------------
__global__ __launch_bounds__(256) void edge_msgs1(
    const float* __restrict__ h, const int* __restrict__ ei,
    const float* __restrict__ esh, const float* __restrict__ ef,
    const float* __restrict__ Wlr, const float* __restrict__ wlsh)
{
    __shared__ float sW[RDIM*DIM];
    __shared__ float swsh[LDIM];
    int tid = threadIdx.x;
    for (int i=tid;i<RDIM*DIM;i+=256) sW[i]=Wlr[i];
    if (tid<LDIM) swsh[tid]=wlsh[tid];
    __syncthreads();
    int e = blockIdx.x*8 + (tid>>5);
    int lane = tid & 31;
    if (e >= E_EDGES) return;
    int src = ei[e], dst = ei[E_EDGES+e];
    float t = (lane<LDIM)? esh[e*LDIM+lane]*swsh[lane] : 0.f;
    float shd = wredsum(t);
    float efv = (lane<RDIM)? ef[e*RDIM+lane] : 0.f;
    int base = lane<<2;
    float g0=0.f,g1=0.f,g2=0.f,g3=0.f;
#pragma unroll
    for (int r=0;r<RDIM;r++){
        float er = __shfl_sync(0xffffffffu, efv, r);
        g0 += er*sW[r*DIM+base+0];
        g1 += er*sW[r*DIM+base+1];
        g2 += er*sW[r*DIM+base+2];
        g3 += er*sW[r*DIM+base+3];
    }
    float4 hv = *(const float4*)(h + src*DIM + base);
    red4(&g_agg1[dst*DIM+base], hv.x*g0*shd, hv.y*g1*shd, hv.z*g2*shd, hv.w*g3*shd);
}

// ----------------- tensor-core 3xTF32 GEMM (64x64 block, 4 warps) ---------------
enum { EPI_NONE=0, EPI_SCORES=1, EPI_ADDPADH=2, EPI_BIASRELU=3, EPI_BIAS=4, EPI_FINAL=5 };

template<int EPI, bool TRANSB, bool GATHER>
__global__ __launch_bounds__(128)
void tcgemm(const float* __restrict__ A, int lda,
            const float* __restrict__ B, int ldb,
            float* __restrict__ C, int ldc,
            int M, int Nc, int K,
            const int* __restrict__ Mdyn,
            const int* __restrict__ gidx,
            const float* __restrict__ ep0,
            const float* __restrict__ ep1,
            float scale)
{
    if (Mdyn) M = *Mdyn;
    int NB = (EPI==EPI_SCORES) ? M : Nc;
    int by = blockIdx.y, bx = blockIdx.x;
    if (by*64 >= M || bx*64 >= NB) return;

    __shared__ float As[32][66];
    __shared__ float Bs[32][72];

    int tid = threadIdx.x;
    int warp = tid>>5, lane = tid&31;
    int wm = (warp&1)<<5, wn = (warp>>1)<<5;
    int gid = lane>>2, tg = lane&3;

    float acc[2][4][4];
#pragma unroll
    for (int i=0;i<2;i++)
#pragma unroll
        for (int j=0;j<4;j++)
#pragma unroll
            for (int k=0;k<4;k++) acc[i][j][k]=0.f;

    for (int k0=0; k0<K; k0+=32){
        // load A tile 64x32 (transpose into As[k][m])
#pragma unroll
        for (int j=0;j<4;j++){
            int idx = tid + j*128;
            int row = idx>>3, c4 = (idx&7)<<2;
            int gr = by*64 + row;
            float4 v = make_float4(0.f,0.f,0.f,0.f);
            if (gr < M){
                int ri = GATHER ? gidx[gr] : gr;
                v = *(const float4*)(A + (size_t)ri*lda + k0 + c4);
            }
            As[c4+0][row]=v.x; As[c4+1][row]=v.y; As[c4+2][row]=v.z; As[c4+3][row]=v.w;
        }
        if (!TRANSB){
#pragma unroll
            for (int j=0;j<4;j++){
                int idx = tid + j*128;
                int kk = idx>>4, n4 = (idx&15)<<2;
                float4 v = *(const float4*)(B + (size_t)(k0+kk)*ldb + bx*64 + n4);
                *(float4*)&Bs[kk][n4] = v;
            }
        } else {
#pragma unroll
            for (int j=0;j<4;j++){
                int idx = tid + j*128;
                int row = idx>>3, c4 = (idx&7)<<2;
                int gn = bx*64 + row;
                float4 v = make_float4(0.f,0.f,0.f,0.f);
                if (gn < NB) v = *(const float4*)(B + (size_t)gn*ldb + k0 + c4);
                Bs[c4+0][row]=v.x; Bs[c4+1][row]=v.y; Bs[c4+2][row]=v.z; Bs[c4+3][row]=v.w;
            }
        }
        __syncthreads();
#pragma unroll
        for (int ks=0; ks<32; ks+=8){
            unsigned ahi[2][4], alo[2][4], bhi[4][2], blo[4][2];
#pragma unroll
            for (int mt=0;mt<2;mt++){
                int rb = wm + mt*16;
                split_tf32(As[ks+tg  ][rb+gid  ], ahi[mt][0], alo[mt][0]);
                split_tf32(As[ks+tg  ][rb+gid+8], ahi[mt][1], alo[mt][1]);
                split_tf32(As[ks+tg+4][rb+gid  ], ahi[mt][2], alo[mt][2]);
                split_tf32(As[ks+tg+4][rb+gid+8], ahi[mt][3], alo[mt][3]);
            }
#pragma unroll
            for (int nt=0;nt<4;nt++){
                int cb = wn + nt*8;
                split_tf32(Bs[ks+tg  ][cb+gid], bhi[nt][0], blo[nt][0]);
                split_tf32(Bs[ks+tg+4][cb+gid], bhi[nt][1], blo[nt][1]);
            }
#pragma unroll
            for (int mt=0;mt<2;mt++)
#pragma unroll
                for (int nt=0;nt<4;nt++){
                    MMA_TF32(acc[mt][nt], ahi[mt][0],ahi[mt][1],ahi[mt][2],ahi[mt][3], bhi[nt][0],bhi[nt][1]);
                    MMA_TF32(acc[mt][nt], ahi[mt][0],ahi[mt][1],ahi[mt][2],ahi[mt][3], blo[nt][0],blo[nt][1]);
                    MMA_TF32(acc[mt][nt], alo[mt][0],alo[mt][1],alo[mt][2],alo[mt][3], bhi[nt][0],bhi[nt][1]);
                }
        }
        __syncthreads();
    }

    // epilogue: c0:(gid,2tg) c1:(gid,2tg+1) c2:(gid+8,2tg) c3:(gid+8,2tg+1)
#pragma unroll
    for (int mt=0;mt<2;mt++){
#pragma unroll
        for (int nt=0;nt<4;nt++){
            int rb = by*64 + wm + mt*16 + gid;
            int cb = bx*64 + wn + nt*8 + (tg<<1);
#pragma unroll
            for (int e=0;e<4;e++){
                int r = rb + ((e>=2)? 8:0);
                int c = cb + (e&1);
                if (r >= M || c >= NB) continue;
                float v = acc[mt][nt][e];
                if constexpr (EPI==EPI_SCORES){
                    v *= scale;
                    if (r==c) v = NEGV;
                } else if constexpr (EPI==EPI_ADDPADH){
                    if (c < DIM) v += ep0[(size_t)r*DIM + c];
                } else if constexpr (EPI==EPI_BIASRELU){
                    v += ep0[c]; v = v>0.f ? v : 0.f;
                } else if constexpr (EPI==EPI_BIAS){
                    v += ep0[c];
                } else if constexpr (EPI==EPI_FINAL){
                    float hl = ep0[(size_t)r*DIM2 + c];
                    float mm = ep1[r];
                    float mfv = (mm > 0.5f) ? 1.f : 0.f;
                    v = (1.f-mm)*hl + mm*((v+hl)*mfv);
                }
                C[(size_t)r*ldc + c] = v;
            }
        }
    }
}

// ----------------- mask MLP output + sigmoid ---------------
__global__ void compute_m(const float* __restrict__ Wms2, const float* __restrict__ bms2)
{
    int row = blockIdx.x*4 + (threadIdx.x>>5);
    int lane = threadIdx.x & 31;
    if (row >= N_NODES) return;
    float s = g_hid[row*HIDD+lane]*Wms2[lane] + g_hid[row*HIDD+lane+32]*Wms2[lane+32];
    s = wredsum(s);
    if (lane==0){
        float z = s + bms2[0];
        float m = 1.f/(1.f+expf(-z));
        g_m[row] = m;
        g_mf[row] = (m > 0.5f) ? 1 : 0;
    }
}

// ----------------- ordered compaction of valid nodes ---------------
__global__ __launch_bounds__(1024) void scan_valid()
{
    __shared__ int cnt[1024];
    int t = threadIdx.x;
    int b = t*4;
    int l0=g_mf[b], l1=g_mf[b+1], l2=g_mf[b+2], l3=g_mf[b+3];
    int c = l0+l1+l2+l3;
    cnt[t]=c; __syncthreads();
    for (int off=1; off<1024; off<<=1){
        int v = cnt[t];
        int add = (t>=off)? cnt[t-off] : 0;
        __syncthreads();
        cnt[t] = v+add;
        __syncthreads();
    }
    int pos = cnt[t]-c;
    if (l0) g_vlist[pos++]=b;
    if (l1) g_vlist[pos++]=b+1;
    if (l2) g_vlist[pos++]=b+2;
    if (l3) g_vlist[pos++]=b+3;
    if (t==1023) g_Nv = cnt[1023];
}

// ----------------- per-row top-16 (tie -> lowest index, matches jax) ---------------
__global__ __launch_bounds__(128) void topk_k()
{
    int Nv = g_Nv;
    int vi = blockIdx.x;
    if (vi >= Nv) return;
    __shared__ float vals[N_NODES];
    __shared__ float rv[128];
    __shared__ int   ri[128];
    int tid = threadIdx.x;
    const float* row = &g_S[(size_t)vi*N_NODES];
    for (int j=tid;j<Nv;j+=128) vals[j]=row[j];
    __syncthreads();
    for (int t=0;t<TOPKK;t++){
        float bv=-3.4e38f; int bi=0x7fffffff;
        for (int j=tid;j<Nv;j+=128){
            float v=vals[j];
            if (v>bv || (v==bv && j<bi)){bv=v;bi=j;}
        }
        rv[tid]=bv; ri[tid]=bi;
        __syncthreads();
        for (int off=64;off>0;off>>=1){
            if (tid<off){
                float ov=rv[tid+off]; int oi=ri[tid+off];
                if (ov>rv[tid] || (ov==rv[tid] && oi<ri[tid])){rv[tid]=ov;ri[tid]=oi;}
            }
            __syncthreads();
        }
        if (tid==0){
            int bj = ri[0];
            if (rv[0] > NEGV*0.5f){
                g_vdc[vi*TOPKK+t]=bj;
                g_vdo[vi*TOPKK+t]=g_vlist[bj];
            } else {
                g_vdc[vi*TOPKK+t]=-1;
                g_vdo[vi*TOPKK+t]=-1;
            }
            vals[bj] = -3.4e38f;
        }
        __syncthreads();
    }
}

// ----------------- virtual edge MLP score ---------------
__global__ __launch_bounds__(256) void vedge_mlp(
    const float* __restrict__ pos, const float* __restrict__ Wa1,
    const float* __restrict__ Wa2, const float* __restrict__ ba2,
    const float* __restrict__ whsh)
{
    __shared__ float sW1[RDIM*SDIM];
    __shared__ float sW2[SDIM];
    int tid=threadIdx.x;
    for (int i=tid;i<RDIM*SDIM;i+=256) sW1[i]=Wa1[2*SDIM*SDIM + i];
    for (int i=tid;i<SDIM;i+=256) sW2[i]=Wa2[i];
    __syncthreads();
    int Nv = g_Nv;
    int s = blockIdx.x*8 + (tid>>5);
    int lane = tid & 31;
    if (s >= Nv*TOPKK) return;
    int jo = g_vdo[s];
    if (jo < 0) return;
    int vi = s >> 4;
    int jc = g_vdc[s];
    int i  = g_vlist[vi];
    float dx = pos[i*3+0]-pos[jo*3+0];
    float dy = pos[i*3+1]-pos[jo*3+1];
    float dz = pos[i*3+2]-pos[jo*3+2];
    float r = sqrtf(dx*dx+dy*dy+dz*dz);
    float rf[8];
#pragma unroll
    for (int k=0;k<8;k++){ float cc=k*(5.0f/7.0f); float d=r-cc; rf[k]=expf(-4.0f*d*d); }
    if (lane < 8){
        float cc=lane*(5.0f/7.0f); float d=r-cc;
        g_rf[s*RDIM+lane] = expf(-4.0f*d*d);
    }
    if (lane==0) g_shd[s] = sh_dot(dx,dy,dz, whsh);
    float sum = 0.f;
#pragma unroll
    for (int u=0;u<4;u++){
        int d = lane + u*32;
        float hv = g_P1[vi*SDIM+d] + g_P2[jc*SDIM+d];
#pragma unroll
        for (int k=0;k<8;k++) hv += rf[k]*sW1[k*SDIM+d];
        hv = hv>0.f ? hv : 0.f;
        sum += hv*sW2[d];
    }
    sum = wredsum(sum);
    if (lane==0){
        float sc = sum + ba2[0];
        g_sc[s] = sc;
        atomicMax(&g_maxenc[jo], enc(sc));
    }
}

// ----------------- softmax denominator ---------------
__global__ void softmax2()
{
    int s = blockIdx.x*blockDim.x + threadIdx.x;
    int Nv = g_Nv;
    if (s >= Nv*TOPKK) return;
    int jo = g_vdo[s];
    if (jo < 0) return;
    float mx = dec(g_maxenc[jo]);
    float e = expf(g_sc[s]-mx);
    g_ex[s] = e;
    atomicAdd(&g_den[jo], e);
}

// ----------------- real-edge hierarchical messages (masked) ---------------
__global__ __launch_bounds__(256) void edge_msgsH(
    const float* __restrict__ pos, const int* __restrict__ ei,
    const float* __restrict__ Whr, const float* __restrict__ whsh)
{
    __shared__ float sW[RDIM*DIM2];
    __shared__ float swsh[LDIM];
    int tid=threadIdx.x;
    for (int i=tid;i<RDIM*DIM2;i+=256) sW[i]=Whr[i];
    if (tid<LDIM) swsh[tid]=whsh[tid];
    __syncthreads();
    int e = blockIdx.x*8 + (tid>>5);
    int lane = tid & 31;
    if (e >= E_EDGES) return;
    int src = ei[e], dst = ei[E_EDGES+e];
    if (!(g_mf[src] & g_mf[dst])) return;
    float dx = pos[src*3+0]-pos[dst*3+0];
    float dy = pos[src*3+1]-pos[dst*3+1];
    float dz = pos[src*3+2]-pos[dst*3+2];
    float r = sqrtf(dx*dx+dy*dy+dz*dz);
    float shd = sh_dot(dx,dy,dz, swsh);
    float rf[8];
#pragma unroll
    for (int k=0;k<8;k++){ float cc=k*(5.0f/7.0f); float d=r-cc; rf[k]=expf(-4.0f*d*d); }
    int base = lane*8;
    float g[8];
#pragma unroll
    for (int u=0;u<8;u++){
        float acc=0.f;
#pragma unroll
        for (int k=0;k<8;k++) acc += rf[k]*sW[k*DIM2+base+u];
        g[u]=acc;
    }
    float4 h0 = *(const float4*)&g_hloc[src*DIM2+base];
    float4 h1 = *(const float4*)&g_hloc[src*DIM2+base+4];
    red4(&g_aggH[dst*DIM2+base  ], h0.x*g[0]*shd, h0.y*g[1]*shd, h0.z*g[2]*shd, h0.w*g[3]*shd);
    red4(&g_aggH[dst*DIM2+base+4], h1.x*g[4]*shd, h1.y*g[5]*shd, h1.z*g[6]*shd, h1.w*g[7]*shd);
}

// ----------------- virtual-edge hierarchical messages ---------------
__global__ __launch_bounds__(256) void virt_msgs(const float* __restrict__ Whr)
{
    __shared__ float sW[RDIM*DIM2];
    int tid=threadIdx.x;
    for (int i=tid;i<RDIM*DIM2;i+=256) sW[i]=Whr[i];
    __syncthreads();
    int Nv = g_Nv;
    int s = blockIdx.x*8 + (tid>>5);
    int lane = tid & 31;
    if (s >= Nv*TOPKK) return;
    int jo = g_vdo[s];
    if (jo < 0) return;
    int vi = s >> 4;
    int i  = g_vlist[vi];
    float wv = g_ex[s]/(g_den[jo]+1e-12f);
    float shd = g_shd[s];
    float rf[8];
#pragma unroll
    for (int k=0;k<8;k++) rf[k]=g_rf[s*RDIM+k]*wv;
    int base = lane*8;
    float g[8];
#pragma unroll
    for (int u=0;u<8;u++){
        float acc=0.f;
#pragma unroll
        for (int k=0;k<8;k++) acc += rf[k]*sW[k*DIM2+base+u];
        g[u]=acc;
    }
    float4 h0 = *(const float4*)&g_hloc[i*DIM2+base];
    float4 h1 = *(const float4*)&g_hloc[i*DIM2+base+4];
    red4(&g_aggH[jo*DIM2+base  ], h0.x*g[0]*shd, h0.y*g[1]*shd, h0.z*g[2]*shd, h0.w*g[3]*shd);
    red4(&g_aggH[jo*DIM2+base+4], h1.x*g[4]*shd, h1.y*g[5]*shd, h1.z*g[6]*shd, h1.w*g[7]*shd);
}

// ----------------- launcher ---------------
extern "C" void kernel_launch(void* const* d_in, const int* in_sizes, int n_in,
                              void* d_out, int out_size)
{
    const float* h    = (const float*)d_in[0];
    const float* pos  = (const float*)d_in[1];
    const int*   ei   = (const int*)  d_in[2];
    const float* esh  = (const float*)d_in[3];
    const float* ef   = (const float*)d_in[4];
    const float* Wlr  = (const float*)d_in[6];
    const float* wlsh = (const float*)d_in[7];
    const float* Wlout= (const float*)d_in[8];
    const float* Wpl  = (const float*)d_in[9];
    const float* Wms1 = (const float*)d_in[10];
    const float* bms1 = (const float*)d_in[11];
    const float* Wms2 = (const float*)d_in[12];
    const float* bms2 = (const float*)d_in[13];
    const float* Wq   = (const float*)d_in[14];
    const float* Wk   = (const float*)d_in[15];
    const float* Wa1  = (const float*)d_in[16];
    const float* ba1  = (const float*)d_in[17];
    const float* Wa2  = (const float*)d_in[18];
    const float* ba2  = (const float*)d_in[19];
    const float* Whr  = (const float*)d_in[20];
    const float* whsh = (const float*)d_in[21];
    const float* Whout= (const float*)d_in[22];
    const float* Wph  = (const float*)d_in[23];
    float* out = (float*)d_out;

    float *p_agg1,*p_hup,*p_hloc,*p_hid,*p_qv,*p_kv,*p_P1,*p_P2,*p_S,*p_aggH,*p_hmup,*p_m;
    int *p_Nv,*p_vlist;
    cudaGetSymbolAddress((void**)&p_agg1, g_agg1);
    cudaGetSymbolAddress((void**)&p_hup , g_hup );
    cudaGetSymbolAddress((void**)&p_hloc, g_hloc);
    cudaGetSymbolAddress((void**)&p_hid , g_hid );
    cudaGetSymbolAddress((void**)&p_qv  , g_qv  );
    cudaGetSymbolAddress((void**)&p_kv  , g_kv  );
    cudaGetSymbolAddress((void**)&p_P1  , g_P1  );
    cudaGetSymbolAddress((void**)&p_P2  , g_P2  );
    cudaGetSymbolAddress((void**)&p_S   , g_S   );
    cudaGetSymbolAddress((void**)&p_aggH, g_aggH);
    cudaGetSymbolAddress((void**)&p_hmup, g_hmup);
    cudaGetSymbolAddress((void**)&p_m   , g_m   );
    cudaGetSymbolAddress((void**)&p_Nv  , g_Nv  );
    cudaGetSymbolAddress((void**)&p_vlist, g_vlist);

    const float scal = 0.088388347648318447f; // 1/sqrt(128)

    fill_k<<<1024,256>>>();
    edge_msgs1<<<E_EDGES/8,256>>>(h,ei,esh,ef,Wlr,wlsh);
    // h_up = agg1 @ W_loc_out
    tcgemm<EPI_NONE,false,false><<<dim3(4,64),128>>>(p_agg1,DIM, Wlout,DIM2, p_hup,DIM2,
        N_NODES,DIM2,DIM, nullptr,nullptr,nullptr,nullptr,0.f);
    // h_local = h_up @ W_prod_loc + pad(h)
    tcgemm<EPI_ADDPADH,false,false><<<dim3(4,64),128>>>(p_hup,DIM2, Wpl,DIM2, p_hloc,DIM2,
        N_NODES,DIM2,DIM2, nullptr,nullptr, h,nullptr,0.f);
    // hidden = relu(h_scalar @ W_ms1 + b_ms1)
    tcgemm<EPI_BIASRELU,false,false><<<dim3(1,64),128>>>(p_hloc,DIM2, Wms1,HIDD, p_hid,HIDD,
        N_NODES,HIDD,SDIM, nullptr,nullptr, bms1,nullptr,0.f);
    compute_m<<<1024,128>>>(Wms2,bms2);
    scan_valid<<<1,1024>>>();
    // gathered valid-row GEMMs
    tcgemm<EPI_NONE,false,true><<<dim3(2,64),128>>>(p_hloc,DIM2, Wq,SDIM, p_qv,SDIM,
        N_NODES,SDIM,SDIM, p_Nv, p_vlist, nullptr,nullptr,0.f);
    tcgemm<EPI_NONE,false,true><<<dim3(2,64),128>>>(p_hloc,DIM2, Wk,SDIM, p_kv,SDIM,
        N_NODES,SDIM,SDIM, p_Nv, p_vlist, nullptr,nullptr,0.f);
    tcgemm<EPI_BIAS,false,true><<<dim3(2,64),128>>>(p_hloc,DIM2, Wa1,SDIM, p_P1,SDIM,
        N_NODES,SDIM,SDIM, p_Nv, p_vlist, ba1,nullptr,0.f);
    tcgemm<EPI_NONE,false,true><<<dim3(2,64),128>>>(p_hloc,DIM2, Wa1+SDIM*SDIM,SDIM, p_P2,SDIM,
        N_NODES,SDIM,SDIM, p_Nv, p_vlist, nullptr,nullptr,0.f);
    // scores = qv @ kv^T * scale, diag=NEG (compact Nv x Nv)
    tcgemm<EPI_SCORES,true,false><<<dim3(64,64),128>>>(p_qv,SDIM, p_kv,SDIM, p_S,N_NODES,
        N_NODES,N_NODES,SDIM, p_Nv, nullptr, nullptr,nullptr, scal);
    topk_k<<<N_NODES,128>>>();
    vedge_mlp<<<N_NODES*TOPKK/8,256>>>(pos, Wa1, Wa2, ba2, whsh);
    softmax2<<<N_NODES*TOPKK/256,256>>>();
    edge_msgsH<<<E_EDGES/8,256>>>(pos,ei,Whr,whsh);
    virt_msgs<<<N_NODES*TOPKK/8,256>>>(Whr);
    // h_m_up = aggH @ W_h_out
    tcgemm<EPI_NONE,false,false><<<dim3(4,64),128>>>(p_aggH,DIM2, Whout,DIM2, p_hmup,DIM2,
        N_NODES,DIM2,DIM2, nullptr,nullptr,nullptr,nullptr,0.f);
    // out = (1-m)*h_local + m*((h_m_up@W_prod_h + h_local)*mf)
    tcgemm<EPI_FINAL,false,false><<<dim3(4,64),128>>>(p_hmup,DIM2, Wph,DIM2, out,DIM2,
        N_NODES,DIM2,DIM2, nullptr,nullptr, p_hloc, p_m, 0.f);
}